// round 13
// baseline (speedup 1.0000x reference)
#include <cuda_runtime.h>
#include <math.h>

// Shapes (fixed per reference setup_inputs)
#define BB    4
#define NRES  300
#define NCLS  80
#define NKPT  17
#define HMW   64
#define HMHW  4096
#define NWRD  10                     // ceil(300/32)
#define MROW  320                    // mask rows padded to NWRD*32
#define NROWS (BB * NRES * NKPT)     // 20400 heatmap rows
#define NMS_T 1024                   // NMS block size

#define IOU_THRF   0.7f
#define SCORE_THRF 0.01f
#define NEGV       (-1000000000.0f)

// Output layout (float32, flattened tuple concat):
// fl [4,300] @0 | fb [4,300,4] @1200 | fs [4,300] @6000 |
// akpts [4,300,17,3] @7200 | vkeep [4,300] @68400
#define OFF_FL 0
#define OFF_FB 1200
#define OFF_FS 6000
#define OFF_AK 7200
#define OFF_VK 68400

// Scratch (device globals — no allocation allowed)
__device__ float g_maxv[NROWS];
__device__ int   g_midx[NROWS];
__device__ int   g_selkv[BB * NRES];        // sel | (kv<<15)
__device__ float g_boxsel[BB * NRES * 4];

// ---------------------------------------------------------------------------
// NMS kernel: 4 blocks x 1024 threads (one block per batch). Triggers PDL so
// the heatmap kernel launches immediately and overlaps with it.
// ---------------------------------------------------------------------------
__global__ __launch_bounds__(NMS_T) void nms_kernel(
    const float* __restrict__ logits,   // [4,300,80]
    const float* __restrict__ boxes,    // [4,300,4] cxcywh
    const float* __restrict__ sizes,    // [4,2]
    float* __restrict__ out)
{
#if __CUDA_ARCH__ >= 900
    cudaTriggerProgrammaticLaunchCompletion();   // all threads: release PDL edge
#endif
    const int tid = threadIdx.x;
    const int b   = blockIdx.x;

    __shared__ float sc[NRES];
    __shared__ int   lb[NRES];
    __shared__ float bx[NRES * 4];
    __shared__ float sv[NRES];
    __shared__ int   order_[NRES];
    __shared__ float obx1[NRES], oby1[NRES], obx2[NRES], oby2[NRES];
    __shared__ float sarea[NRES];
    __shared__ unsigned mask[MROW * NWRD];   // rows >= NRES never used (kj=0)
    __shared__ unsigned vw[NWRD];            // valid bits, sorted order
    __shared__ unsigned kw[NWRD];            // keep bits (filled by greedy)
    __shared__ int   ti[NRES];
    __shared__ float red[NMS_T / 32];
    __shared__ float sM;

    const float s0 = sizes[b * 2 + 0];
    const float s1 = sizes[b * 2 + 1];

    // ---- phase 1: logits argmax + sigmoid + abs box; fused |box| max ----
    float lmax = 0.0f;
    if (tid < NRES) {
        const int r = tid;
        const float4* lrow = (const float4*)(logits + ((size_t)b * NRES + r) * NCLS);
        float mv = -3.402823466e38f; int mi = 0;
        #pragma unroll 5
        for (int c4 = 0; c4 < NCLS / 4; c4++) {
            float4 v = lrow[c4];
            int cb = c4 * 4;
            if (v.x > mv) { mv = v.x; mi = cb;     }
            if (v.y > mv) { mv = v.y; mi = cb + 1; }
            if (v.z > mv) { mv = v.z; mi = cb + 2; }
            if (v.w > mv) { mv = v.w; mi = cb + 3; }
        }
        float score = 1.0f / (1.0f + expf(-mv));
        sc[r] = score;
        lb[r] = mi;

        const float4 brow = *(const float4*)(boxes + ((size_t)b * NRES + r) * 4);
        float x1 = (brow.x - brow.z * 0.5f) * s0;
        float y1 = (brow.y - brow.w * 0.5f) * s1;
        float x2 = (brow.x + brow.z * 0.5f) * s0;
        float y2 = (brow.y + brow.w * 0.5f) * s1;
        bx[r * 4 + 0] = x1;
        bx[r * 4 + 1] = y1;
        bx[r * 4 + 2] = x2;
        bx[r * 4 + 3] = y2;
        lmax = fmaxf(fmaxf(fabsf(x1), fabsf(y1)), fmaxf(fabsf(x2), fabsf(y2)));
        sv[r] = (score > SCORE_THRF) ? score : NEGV;
    }
    #pragma unroll
    for (int o = 16; o; o >>= 1)
        lmax = fmaxf(lmax, __shfl_xor_sync(0xffffffffu, lmax, o));
    if ((tid & 31) == 0) red[tid >> 5] = lmax;
    __syncthreads();
    if (tid < 32) {
        float v = red[tid];
        #pragma unroll
        for (int o = 16; o; o >>= 1)
            v = fmaxf(v, __shfl_xor_sync(0xffffffffu, v, o));
        if (tid == 0) sM = v + 1.0f;
    }
    __syncthreads();
    const float maxc = sM;

    // ---- phase 2: stable descending rank (stable argsort(-s)) ----
    if (tid < NRES) {
        const int r = tid;
        float si = sv[r];
        int rk = 0;
        #pragma unroll 4
        for (int j = 0; j < NRES; j++) {
            float sj = sv[j];
            rk += (sj > si) || (sj == si && j < r);
        }
        order_[rk] = r;
    }
    __syncthreads();

    // ---- phase 3: sorted class-offset boxes (SoA) + areas + valid bits ----
    {
        int valid = 0;
        if (tid < NRES) {
            const int t = tid;
            int i = order_[t];
            valid = sv[i] != NEGV;
            float off = (float)lb[i] * maxc;
            float x1 = bx[i * 4 + 0] + off;
            float y1 = bx[i * 4 + 1] + off;
            float x2 = bx[i * 4 + 2] + off;
            float y2 = bx[i * 4 + 3] + off;
            obx1[t] = x1; oby1[t] = y1; obx2[t] = x2; oby2[t] = y2;
            sarea[t] = (x2 - x1) * (y2 - y1);
        }
        if (tid < MROW) {   // warps 0..9 fully active -> safe full-mask ballot
            unsigned bal = __ballot_sync(0xffffffffu, valid);
            if ((tid & 31) == 0) vw[tid >> 5] = bal;
        }
    }
    __syncthreads();

    // ---- phase 4: suppression bitmask; whole-word skip for lower triangle
    //      (word w has any j>r only if w*32+31 > r; guard is warp-uniform
    //       for consecutive-r lanes). FP math identical to reference. ----
    for (int task = tid; task < NRES * NWRD; task += NMS_T) {
        int r = task % NRES;
        int w = task / NRES;
        unsigned m = 0;
        int j0 = w * 32;
        if (j0 + 31 > r) {
            float x1 = obx1[r], y1 = oby1[r], x2 = obx2[r], y2 = oby2[r];
            float ar = sarea[r];
            #pragma unroll 8
            for (int jj = 0; jj < 32; jj++) {
                int j = j0 + jj;
                if (j > r && j < NRES) {
                    float iw = fmaxf(fminf(x2, obx2[j]) - fmaxf(x1, obx1[j]), 0.0f);
                    float ih = fmaxf(fminf(y2, oby2[j]) - fmaxf(y1, oby1[j]), 0.0f);
                    float inter = iw * ih;
                    float iou = inter / (ar + sarea[j] - inter + 1e-9f);
                    if (iou > IOU_THRF) m |= (1u << jj);
                }
            }
        }
        mask[r * NWRD + w] = m;
    }
    __syncthreads();

    // ---- phase 5: chunked greedy (warp 0). Lane c resolves its own 32-row
    //      word locally (no shfl on the chain), then one broadcast + parallel
    //      mask-OR per chunk. Emits kw words directly. ----
    if (tid < 32) {
        unsigned sw = 0;                 // lane's suppression word
        const bool ld = tid < NWRD;
        #pragma unroll
        for (int c = 0; c < NWRD; c++) {
            unsigned kwc = 0;
            if (tid == c) {
                unsigned vb = vw[c];
                #pragma unroll 8
                for (int j = 0; j < 32; j++) {
                    unsigned mj = mask[(c * 32 + j) * NWRD + c];
                    unsigned kj = (vb >> j) & (~sw >> j) & 1u;
                    kwc |= kj << j;
                    sw |= kj ? mj : 0u;
                }
                kw[c] = kwc;
            }
            unsigned word = __shfl_sync(0xffffffffu, kwc, c);
            unsigned wrem = word;
            while (wrem) {
                int j = __ffs(wrem) - 1;
                wrem &= wrem - 1u;
                if (ld) sw |= mask[(c * 32 + j) * NWRD + tid];
            }
        }
    }
    __syncthreads();

    // ---- phase 6: ti = kept (sorted order) then suppressed (ascending) ----
    if (tid < NRES) {
        const int t = tid;
        int wt = t >> 5, bt_ = t & 31;
        int cnt = 0, K = 0;
        #pragma unroll
        for (int w = 0; w < NWRD; w++) {
            int pc = __popc(kw[w]);
            K += pc;
            if (w < wt) cnt += pc;
        }
        cnt += __popc(kw[wt] & ((1u << bt_) - 1u));
        int kp = (kw[wt] >> bt_) & 1u;
        int p = kp ? cnt : (K + t - cnt);
        ti[p] = t;
    }
    __syncthreads();

    // ---- phase 7: outputs + scratch for finalize ----
    if (tid < NRES) {
        const int t = tid;
        int tt  = ti[t];
        int kv  = (kw[tt >> 5] >> (tt & 31)) & 1u;
        int sel = order_[tt];
        int gi  = b * NRES + t;

        g_selkv[gi] = sel | (kv << 15);

        float b0 = bx[sel * 4 + 0], b1 = bx[sel * 4 + 1];
        float b2 = bx[sel * 4 + 2], b3 = bx[sel * 4 + 3];
        g_boxsel[gi * 4 + 0] = b0;
        g_boxsel[gi * 4 + 1] = b1;
        g_boxsel[gi * 4 + 2] = b2;
        g_boxsel[gi * 4 + 3] = b3;

        out[OFF_FL + gi] = kv ? (float)lb[sel] : -1.0f;
        float* fb = out + OFF_FB + (size_t)gi * 4;
        fb[0] = kv ? b0 : 0.0f;
        fb[1] = kv ? b1 : 0.0f;
        fb[2] = kv ? b2 : 0.0f;
        fb[3] = kv ? b3 : 0.0f;
        out[OFF_FS + gi] = kv ? sc[sel] : 0.0f;
        out[OFF_VK + gi] = kv ? 1.0f : 0.0f;
    }
}

// ---------------------------------------------------------------------------
// Heatmap kernel: 2 rows per 256-thread block. 8 front-batched float4 loads
// per thread (2x MLP vs 1-row version); reduction overhead amortized over
// 32 KB; argmax rescan runs on live registers (no reload pass).
// ---------------------------------------------------------------------------
__global__ __launch_bounds__(256) void hm_kernel(const float* __restrict__ hm)
{
    const int row0 = blockIdx.x * 2;
    const float4* r4 = (const float4*)hm + (size_t)row0 * (HMHW / 4);
    const int tid = threadIdx.x;

    __shared__ float red[16];          // 8 warps x 2 rows
    __shared__ float sMa, sMb;
    __shared__ int   sIa, sIb;

    // row 0: float4 indices tid + q*256 (q=0..3); row 1: +1024
    float4 a0 = r4[tid];
    float4 a1 = r4[tid + 256];
    float4 a2 = r4[tid + 512];
    float4 a3 = r4[tid + 768];
    float4 b0 = r4[tid + 1024];
    float4 b1 = r4[tid + 1280];
    float4 b2 = r4[tid + 1536];
    float4 b3 = r4[tid + 1792];

    float ta = fmaxf(
        fmaxf(fmaxf(fmaxf(a0.x, a0.y), fmaxf(a0.z, a0.w)),
              fmaxf(fmaxf(a1.x, a1.y), fmaxf(a1.z, a1.w))),
        fmaxf(fmaxf(fmaxf(a2.x, a2.y), fmaxf(a2.z, a2.w)),
              fmaxf(fmaxf(a3.x, a3.y), fmaxf(a3.z, a3.w))));
    float tb = fmaxf(
        fmaxf(fmaxf(fmaxf(b0.x, b0.y), fmaxf(b0.z, b0.w)),
              fmaxf(fmaxf(b1.x, b1.y), fmaxf(b1.z, b1.w))),
        fmaxf(fmaxf(fmaxf(b2.x, b2.y), fmaxf(b2.z, b2.w)),
              fmaxf(fmaxf(b3.x, b3.y), fmaxf(b3.z, b3.w))));

    float wa = ta, wb = tb;
    #pragma unroll
    for (int o = 16; o; o >>= 1) {
        wa = fmaxf(wa, __shfl_xor_sync(0xffffffffu, wa, o));
        wb = fmaxf(wb, __shfl_xor_sync(0xffffffffu, wb, o));
    }
    if ((tid & 31) == 0) { red[tid >> 5] = wa; red[8 + (tid >> 5)] = wb; }
    if (tid == 0) { sIa = 0x7fffffff; sIb = 0x7fffffff; }
    __syncthreads();
    if (tid == 0) {
        float M = red[0];
        #pragma unroll
        for (int w = 1; w < 8; w++) M = fmaxf(M, red[w]);
        sMa = M;
    }
    if (tid == 1) {
        float M = red[8];
        #pragma unroll
        for (int w = 1; w < 8; w++) M = fmaxf(M, red[8 + w]);
        sMb = M;
    }
    __syncthreads();
    const float Ma = sMa, Mb = sMb;

    // rescan live registers, descending -> last write wins = smallest index
    if (ta == Ma) {
        int g = 0;
        #pragma unroll
        for (int q = 3; q >= 0; q--) {
            float4 v = (q == 0) ? a0 : (q == 1) ? a1 : (q == 2) ? a2 : a3;
            int base = 4 * (tid + q * 256);
            if (v.w == Ma) g = base + 3;
            if (v.z == Ma) g = base + 2;
            if (v.y == Ma) g = base + 1;
            if (v.x == Ma) g = base;
        }
        atomicMin(&sIa, g);
    }
    if (tb == Mb) {
        int g = 0;
        #pragma unroll
        for (int q = 3; q >= 0; q--) {
            float4 v = (q == 0) ? b0 : (q == 1) ? b1 : (q == 2) ? b2 : b3;
            int base = 4 * (tid + q * 256);
            if (v.w == Mb) g = base + 3;
            if (v.z == Mb) g = base + 2;
            if (v.y == Mb) g = base + 1;
            if (v.x == Mb) g = base;
        }
        atomicMin(&sIb, g);
    }
    __syncthreads();
    if (tid == 0) { g_maxv[row0]     = Ma; g_midx[row0]     = sIa; }
    if (tid == 1) { g_maxv[row0 + 1] = Mb; g_midx[row0 + 1] = sIb; }
}

// ---------------------------------------------------------------------------
// Finalize: gather (maxv, idx) by sel, compute akpts. One thread per output.
// ---------------------------------------------------------------------------
__global__ __launch_bounds__(64) void finalize_kernel(
    const float* __restrict__ koff,   // [4,300,17,2]
    float* __restrict__ out)
{
    int i = blockIdx.x * 64 + threadIdx.x;   // (b, t, k) flattened
    if (i >= NROWS) return;
    int k  = i % NKPT;
    int gi = i / NKPT;
    int b  = gi / NRES;

    int sk  = g_selkv[gi];
    int sel = sk & 0x7fff;
    int kv  = sk >> 15;
    int row = (b * NRES + sel) * NKPT + k;

    float mv = g_maxv[row];
    int   bi = g_midx[row];
    float2 ko = *(const float2*)(koff + (size_t)row * 2);

    float nx = fminf(fmaxf(__int2float_rn(bi & (HMW - 1)) / (float)(HMW - 1) + ko.x, 0.0f), 1.0f);
    float ny = fminf(fmaxf(__int2float_rn(bi >> 6)        / (float)(HMW - 1) + ko.y, 0.0f), 1.0f);

    float x1 = g_boxsel[gi * 4 + 0], y1 = g_boxsel[gi * 4 + 1];
    float x2 = g_boxsel[gi * 4 + 2], y2 = g_boxsel[gi * 4 + 3];
    float ax = x1 + nx * (x2 - x1);
    float ay = y1 + ny * (y2 - y1);

    float* o = out + OFF_AK + (size_t)i * 3;
    o[0] = kv ? ax : 0.0f;
    o[1] = kv ? ay : 0.0f;
    o[2] = kv ? mv : 0.0f;
}

// ---------------------------------------------------------------------------
extern "C" void kernel_launch(void* const* d_in, const int* in_sizes, int n_in,
                              void* d_out, int out_size)
{
    const float* logits = (const float*)d_in[0];  // pred_logits
    const float* boxes  = (const float*)d_in[1];  // pred_boxes
    const float* hm     = (const float*)d_in[2];  // pred_keypoint_heatmaps
    const float* koff   = (const float*)d_in[3];  // pred_keypoint_offsets
    const float* sizes  = (const float*)d_in[4];  // orig_target_sizes
    float* out = (float*)d_out;

    // 1) NMS first (4 blocks x 1024 threads); triggers PDL edge at entry.
    nms_kernel<<<BB, NMS_T>>>(logits, boxes, sizes, out);

    // 2) Heatmap stream (2 rows/block) with programmatic dependent launch:
    //    overlaps NMS. Deterministic fallback to a plain launch if PDL fails.
    cudaLaunchConfig_t cfg = {};
    cfg.gridDim  = dim3(NROWS / 2);
    cfg.blockDim = dim3(256);
    cfg.stream   = 0;
    cudaLaunchAttribute at[1];
    at[0].id = cudaLaunchAttributeProgrammaticStreamSerialization;
    at[0].val.programmaticStreamSerializationAllowed = 1;
    cfg.attrs = at;
    cfg.numAttrs = 1;
    if (cudaLaunchKernelEx(&cfg, hm_kernel, hm) != cudaSuccess) {
        hm_kernel<<<NROWS / 2, 256>>>(hm);
    }

    // 3) Finalize: stream-ordered after both (PDL preserves downstream order).
    finalize_kernel<<<(NROWS + 63) / 64, 64>>>(koff, out);
}